// round 6
// baseline (speedup 1.0000x reference)
#include <cuda_runtime.h>
#include <cuda_fp16.h>

#define NN 40000
#define EE 640000
#define HD 128
#define GG 64
#define PADH 136   // padded halves per smem row (conflict-free ldmatrix)

// ---------------- scratch (no allocs: __device__ globals) -------------------
__device__ __align__(16) float  g_xw  [(size_t)NN * HD];   // x@W f32
__device__ __align__(16) __half g_xwh [(size_t)NN * HD];   // x@W fp16 (gather)
__device__ __align__(16) float  g_h   [(size_t)NN * HD];   // layer output f32
__device__ __align__(16) int    g_degi[NN];
__device__ __align__(16) float  g_dinv[NN];
__device__ __align__(16) int    g_src [EE];
__device__ __align__(16) int    g_dst [EE];
__device__ __align__(16) int    g_adj [EE];                // CSR: src sorted by dst
__device__ __align__(16) int    g_rowstart[NN + 1];
__device__ __align__(16) int    g_cursor[NN];
__device__ __align__(16) int    g_gstart[GG + 1];
__device__ int g_is64;

__device__ __forceinline__ int IDX(const void* p, long long pos) {
    return g_is64 ? (int)((const long long*)p)[pos] : ((const int*)p)[pos];
}

// ---------------- dtype detection (reads first 32KB only) -------------------
__global__ void detect_kernel(const unsigned int* __restrict__ raw) {
    __shared__ int nz;
    if (threadIdx.x == 0) nz = 0;
    __syncthreads();
    int cnt = 0;
    for (int j = threadIdx.x; j < 4096; j += 256)
        if (raw[2 * j + 1] != 0u) cnt++;
    atomicAdd(&nz, cnt);
    __syncthreads();
    if (threadIdx.x == 0) g_is64 = (nz < 64) ? 1 : 0;
}

// ---------------- prep ------------------------------------------------------
__global__ void zero_misc_kernel() {
    int i = blockIdx.x * blockDim.x + threadIdx.x;
    if (i < NN) { g_degi[i] = 0; g_cursor[i] = 0; }
    if (i <= GG) g_gstart[i] = NN;
}

// index convert + in-degree histogram
__global__ void conv_deg_kernel(const void* __restrict__ ei) {
    int i = blockIdx.x * blockDim.x + threadIdx.x;
    if (i >= EE) return;
    int s = IDX(ei, i);
    int d = IDX(ei, (long long)EE + i);
    g_src[i] = s;
    g_dst[i] = d;
    atomicAdd(&g_degi[d], 1);
}

// single-block exclusive prefix sum over g_degi -> g_rowstart
__global__ __launch_bounds__(1024) void prefix_kernel() {
    int t = threadIdx.x;
    int base = t * 40;                 // 1024*40 >= 40000
    int s = 0;
    for (int j = 0; j < 40; j++) {
        int idx = base + j;
        if (idx < NN) s += g_degi[idx];
    }
    int lane = t & 31, wid = t >> 5;
    int v = s;
#pragma unroll
    for (int o = 1; o < 32; o <<= 1) {
        int u = __shfl_up_sync(~0u, v, o);
        if (lane >= o) v += u;
    }
    __shared__ int ws[32];
    if (lane == 31) ws[wid] = v;
    __syncthreads();
    if (wid == 0) {
        int w = ws[lane];
#pragma unroll
        for (int o = 1; o < 32; o <<= 1) {
            int u = __shfl_up_sync(~0u, w, o);
            if (lane >= o) w += u;
        }
        ws[lane] = w;
    }
    __syncthreads();
    int run = v - s + (wid ? ws[wid - 1] : 0);
    for (int j = 0; j < 40; j++) {
        int idx = base + j;
        if (idx < NN) { g_rowstart[idx] = run; run += g_degi[idx]; }
    }
    if (t == 0) g_rowstart[NN] = EE;
}

__global__ void dinv_kernel() {
    int i = blockIdx.x * blockDim.x + threadIdx.x;
    if (i < NN) g_dinv[i] = rsqrtf((float)g_degi[i] + 1.0f);
}

// graph boundaries from sorted batch (no atomics)
__global__ void gstart_kernel(const void* __restrict__ batch) {
    int i = blockIdx.x * blockDim.x + threadIdx.x;
    if (i >= NN) return;
    int b  = IDX(batch, i);
    int bp = i ? IDX(batch, i - 1) : -1;
    for (int g = bp + 1; g <= b; g++) g_gstart[g] = i;
}

// scatter edges into CSR slots
__global__ void scatter_kernel() {
    int i = blockIdx.x * blockDim.x + threadIdx.x;
    if (i >= EE) return;
    int d = g_dst[i];
    int pos = g_rowstart[d] + atomicAdd(&g_cursor[d], 1);
    g_adj[pos] = g_src[i];
}

// ---------------- tensor-core GEMM: C[M,128] = A[M,128] @ W[128,128] --------
__global__ __launch_bounds__(256) void gemm_tc_kernel(const float* __restrict__ A,
                                                      const float* __restrict__ W) {
    extern __shared__ __half smh[];
    __half* As = smh;                 // [128][PADH]
    __half* Bs = smh + 128 * PADH;    // [128][PADH]  (Bs[k][n])

    int tid = threadIdx.x;
    long long mbase = (long long)blockIdx.x * 128;

#pragma unroll
    for (int i = 0; i < 16; i++) {
        int idx = i * 256 + tid;
        int row = idx >> 5, c4 = idx & 31;
        long long grow = mbase + row;
        float4 v = (grow < NN) ? ((const float4*)A)[grow * 32 + c4]
                               : make_float4(0.f, 0.f, 0.f, 0.f);
        __half2* dst = (__half2*)(As + row * PADH + c4 * 4);
        dst[0] = __floats2half2_rn(v.x, v.y);
        dst[1] = __floats2half2_rn(v.z, v.w);
    }
#pragma unroll
    for (int i = 0; i < 16; i++) {
        int idx = i * 256 + tid;
        int row = idx >> 5, c4 = idx & 31;
        float4 v = ((const float4*)W)[row * 32 + c4];
        __half2* dst = (__half2*)(Bs + row * PADH + c4 * 4);
        dst[0] = __floats2half2_rn(v.x, v.y);
        dst[1] = __floats2half2_rn(v.z, v.w);
    }
    __syncthreads();

    int wid = tid >> 5, lane = tid & 31;
    int wm = (wid & 3) * 32;
    int wn = (wid >> 2) * 64;

    float acc[2][8][4];
#pragma unroll
    for (int mt = 0; mt < 2; mt++)
#pragma unroll
        for (int nt = 0; nt < 8; nt++)
#pragma unroll
            for (int q = 0; q < 4; q++) acc[mt][nt][q] = 0.f;

#pragma unroll
    for (int kk = 0; kk < 8; kk++) {
        unsigned a[2][4];
#pragma unroll
        for (int mt = 0; mt < 2; mt++) {
            int r = lane & 15, c = (lane >> 4) * 8;
            unsigned addr = (unsigned)__cvta_generic_to_shared(
                As + (wm + mt * 16 + r) * PADH + kk * 16 + c);
            asm volatile("ldmatrix.sync.aligned.m8n8.x4.shared.b16 {%0,%1,%2,%3}, [%4];"
                         : "=r"(a[mt][0]), "=r"(a[mt][1]), "=r"(a[mt][2]), "=r"(a[mt][3])
                         : "r"(addr));
        }
        unsigned b[8][2];
#pragma unroll
        for (int nt2 = 0; nt2 < 4; nt2++) {
            int krow = kk * 16 + ((lane >> 3) & 1) * 8 + (lane & 7);
            int ncol = wn + nt2 * 16 + (lane >> 4) * 8;
            unsigned addr = (unsigned)__cvta_generic_to_shared(Bs + krow * PADH + ncol);
            asm volatile("ldmatrix.sync.aligned.m8n8.x4.trans.shared.b16 {%0,%1,%2,%3}, [%4];"
                         : "=r"(b[nt2 * 2][0]), "=r"(b[nt2 * 2][1]),
                           "=r"(b[nt2 * 2 + 1][0]), "=r"(b[nt2 * 2 + 1][1])
                         : "r"(addr));
        }
#pragma unroll
        for (int mt = 0; mt < 2; mt++)
#pragma unroll
            for (int nt = 0; nt < 8; nt++)
                asm volatile("mma.sync.aligned.m16n8k16.row.col.f32.f16.f16.f32 "
                             "{%0,%1,%2,%3}, {%4,%5,%6,%7}, {%8,%9}, {%0,%1,%2,%3};"
                             : "+f"(acc[mt][nt][0]), "+f"(acc[mt][nt][1]),
                               "+f"(acc[mt][nt][2]), "+f"(acc[mt][nt][3])
                             : "r"(a[mt][0]), "r"(a[mt][1]), "r"(a[mt][2]), "r"(a[mt][3]),
                               "r"(b[nt][0]), "r"(b[nt][1]));
    }

    int r0 = lane >> 2, cq = (lane & 3) * 2;
#pragma unroll
    for (int mt = 0; mt < 2; mt++) {
        long long rowA = mbase + wm + mt * 16 + r0;
        long long rowB = rowA + 8;
#pragma unroll
        for (int nt = 0; nt < 8; nt++) {
            int col = wn + nt * 8 + cq;
            if (rowA < NN) {
                *(float2*)&g_xw[rowA * HD + col] = make_float2(acc[mt][nt][0], acc[mt][nt][1]);
                *(__half2*)&g_xwh[rowA * HD + col] = __floats2half2_rn(acc[mt][nt][0], acc[mt][nt][1]);
            }
            if (rowB < NN) {
                *(float2*)&g_xw[rowB * HD + col] = make_float2(acc[mt][nt][2], acc[mt][nt][3]);
                *(__half2*)&g_xwh[rowB * HD + col] = __floats2half2_rn(acc[mt][nt][2], acc[mt][nt][3]);
            }
        }
    }
}

// ---------------- node-centric aggregation + epilogue -----------------------
// 16 lanes per node; f32 register accumulation; h = relu(agg + xw*dinv^2 + b)
__device__ __forceinline__ void accum8(float* acc, uint4 v, float nm) {
    __half2* hv = (__half2*)&v;
#pragma unroll
    for (int i = 0; i < 4; i++) {
        float2 f = __half22float2(hv[i]);
        acc[2 * i]     = fmaf(f.x, nm, acc[2 * i]);
        acc[2 * i + 1] = fmaf(f.y, nm, acc[2 * i + 1]);
    }
}

__global__ __launch_bounds__(256) void agg_kernel(const float* __restrict__ b) {
    int tid = threadIdx.x;
    int grp = tid >> 4, l16 = tid & 15;
    int n = blockIdx.x * 16 + grp;        // 2500 * 16 = 40000 exact
    int beg = g_rowstart[n], end = g_rowstart[n + 1];
    float dn = g_dinv[n];

    float acc[8] = {0.f, 0.f, 0.f, 0.f, 0.f, 0.f, 0.f, 0.f};
    int e = beg;
    while (e + 2 <= end) {
        int s0 = g_adj[e], s1 = g_adj[e + 1];
        uint4 v0 = ((const uint4*)g_xwh)[(size_t)s0 * 16 + l16];
        uint4 v1 = ((const uint4*)g_xwh)[(size_t)s1 * 16 + l16];
        float nm0 = dn * __ldg(&g_dinv[s0]);
        float nm1 = dn * __ldg(&g_dinv[s1]);
        accum8(acc, v0, nm0);
        accum8(acc, v1, nm1);
        e += 2;
    }
    if (e < end) {
        int s0 = g_adj[e];
        uint4 v0 = ((const uint4*)g_xwh)[(size_t)s0 * 16 + l16];
        accum8(acc, v0, dn * __ldg(&g_dinv[s0]));
    }

    float dd = dn * dn;
    const float4* wrow = (const float4*)(g_xw + (size_t)n * HD);
    float4 w0 = wrow[l16 * 2], w1 = wrow[l16 * 2 + 1];
    float4 bb0 = ((const float4*)b)[l16 * 2], bb1 = ((const float4*)b)[l16 * 2 + 1];
    float4 h0, h1;
    h0.x = fmaxf(fmaf(w0.x, dd, acc[0]) + bb0.x, 0.f);
    h0.y = fmaxf(fmaf(w0.y, dd, acc[1]) + bb0.y, 0.f);
    h0.z = fmaxf(fmaf(w0.z, dd, acc[2]) + bb0.z, 0.f);
    h0.w = fmaxf(fmaf(w0.w, dd, acc[3]) + bb0.w, 0.f);
    h1.x = fmaxf(fmaf(w1.x, dd, acc[4]) + bb1.x, 0.f);
    h1.y = fmaxf(fmaf(w1.y, dd, acc[5]) + bb1.y, 0.f);
    h1.z = fmaxf(fmaf(w1.z, dd, acc[6]) + bb1.z, 0.f);
    h1.w = fmaxf(fmaf(w1.w, dd, acc[7]) + bb1.w, 0.f);
    float4* hrow = (float4*)(g_h + (size_t)n * HD);
    hrow[l16 * 2]     = h0;
    hrow[l16 * 2 + 1] = h1;
}

// ---------------- mean pool: one block per graph, no atomics ----------------
__global__ __launch_bounds__(128) void pool_kernel(float* __restrict__ out) {
    int g = blockIdx.x, t = threadIdx.x;
    int beg = g_gstart[g], end = g_gstart[g + 1];
    float s = 0.f;
#pragma unroll 4
    for (int n = beg; n < end; n++) s += g_h[(size_t)n * HD + t];
    out[g * HD + t] = s / fmaxf((float)(end - beg), 1.0f);
}

// ---------------- launch -----------------------------------------------------
extern "C" void kernel_launch(void* const* d_in, const int* in_sizes, int n_in,
                              void* d_out, int out_size) {
    const float *x = 0, *W1 = 0, *b1 = 0, *W2 = 0, *b2 = 0;
    const void  *ei = 0, *batch = 0;
    for (int i = 0; i < n_in; i++) {
        long long sz = in_sizes[i];
        if      (sz == (long long)NN * HD) x = (const float*)d_in[i];
        else if (sz == 2LL * EE)           ei = d_in[i];
        else if (sz == NN)                 batch = d_in[i];
        else if (sz == HD * HD) { if (!W1) W1 = (const float*)d_in[i];
                                  else     W2 = (const float*)d_in[i]; }
        else if (sz == HD)      { if (!b1) b1 = (const float*)d_in[i];
                                  else     b2 = (const float*)d_in[i]; }
    }
    float* out = (float*)d_out;

    static cudaStream_t sA = 0;
    static cudaEvent_t ev0 = 0, ev1 = 0;
    static void* h_addr = 0;
    if (!sA) {
        cudaStreamCreateWithFlags(&sA, cudaStreamNonBlocking);
        cudaEventCreateWithFlags(&ev0, cudaEventDisableTiming);
        cudaEventCreateWithFlags(&ev1, cudaEventDisableTiming);
        cudaGetSymbolAddress(&h_addr, g_h);
        cudaFuncSetAttribute((const void*)gemm_tc_kernel,
                             cudaFuncAttributeMaxDynamicSharedMemorySize,
                             2 * 128 * PADH * (int)sizeof(__half));
    }

    const int ZB    = (NN + 255) / 256;       // 157
    const int EB    = (EE + 255) / 256;       // 2500
    const int GEMMB = (NN + 127) / 128;       // 313
    const int GSM   = 2 * 128 * PADH * (int)sizeof(__half);

    // fork: GEMM1 on sA; CSR build chain on main stream
    cudaEventRecord(ev0, 0);
    cudaStreamWaitEvent(sA, ev0, 0);
    gemm_tc_kernel<<<GEMMB, 256, GSM, sA>>>(x, W1);
    cudaEventRecord(ev1, sA);

    detect_kernel<<<1, 256>>>((const unsigned int*)ei);
    zero_misc_kernel<<<ZB, 256>>>();
    conv_deg_kernel<<<EB, 256>>>(ei);
    prefix_kernel<<<1, 1024>>>();
    dinv_kernel<<<ZB, 256>>>();
    gstart_kernel<<<ZB, 256>>>(batch);
    scatter_kernel<<<EB, 256>>>();

    // join: layer 1
    cudaStreamWaitEvent(0, ev1, 0);
    agg_kernel<<<2500, 256>>>(b1);

    // layer 2 (serial: GEMM2 reads g_h)
    gemm_tc_kernel<<<GEMMB, 256, GSM>>>((const float*)h_addr, W2);
    agg_kernel<<<2500, 256>>>(b2);

    // pool
    pool_kernel<<<GG, 128>>>(out);
}

// round 7
// speedup vs baseline: 1.1474x; 1.1474x over previous
#include <cuda_runtime.h>
#include <cuda_fp16.h>

#define NN 40000
#define EE 640000
#define HD 128
#define GG 64
#define PADH 136   // padded halves per smem row (conflict-free ldmatrix)

// ---------------- scratch (no allocs: __device__ globals) -------------------
__device__ __align__(16) float  g_xw  [(size_t)NN * HD];   // x@W f32
__device__ __align__(16) __half g_xwh [(size_t)NN * HD];   // x@W fp16 (gather)
__device__ __align__(16) __half g_aggh[(size_t)NN * HD];   // fp16 edge accum
__device__ __align__(16) float  g_h   [(size_t)NN * HD];   // layer output f32
__device__ __align__(16) int    g_degi[NN];
__device__ __align__(16) float  g_dinv[NN];
__device__ __align__(16) int    g_src [EE];
__device__ __align__(16) int    g_dst [EE];
__device__ __align__(16) int    g_gstart[GG + 1];
__device__ int g_is64;

__device__ __forceinline__ int IDX(const void* p, long long pos) {
    return g_is64 ? (int)((const long long*)p)[pos] : ((const int*)p)[pos];
}

// ---------------- dtype detection (reads first 32KB only) -------------------
__global__ void detect_kernel(const unsigned int* __restrict__ raw) {
    __shared__ int nz;
    if (threadIdx.x == 0) nz = 0;
    __syncthreads();
    int cnt = 0;
    for (int j = threadIdx.x; j < 4096; j += 256)
        if (raw[2 * j + 1] != 0u) cnt++;
    atomicAdd(&nz, cnt);
    __syncthreads();
    if (threadIdx.x == 0) g_is64 = (nz < 64) ? 1 : 0;
}

// ---------------- prep ------------------------------------------------------
__global__ void zero_misc_kernel() {
    int i = blockIdx.x * blockDim.x + threadIdx.x;
    if (i < NN) g_degi[i] = 0;
    if (i <= GG) g_gstart[i] = NN;
}

// index convert + in-degree histogram (int atomics; no 64-bin count atomics)
__global__ void conv_deg_kernel(const void* __restrict__ ei) {
    int i = blockIdx.x * blockDim.x + threadIdx.x;
    if (i >= EE) return;
    int s = IDX(ei, i);
    int d = IDX(ei, (long long)EE + i);
    g_src[i] = s;
    g_dst[i] = d;
    atomicAdd(&g_degi[d], 1);
}

__global__ void dinv_kernel() {
    int i = blockIdx.x * blockDim.x + threadIdx.x;
    if (i < NN) g_dinv[i] = rsqrtf((float)g_degi[i] + 1.0f);
}

// graph boundaries from sorted batch (no atomics)
__global__ void gstart_kernel(const void* __restrict__ batch) {
    int i = blockIdx.x * blockDim.x + threadIdx.x;
    if (i >= NN) return;
    int b  = IDX(batch, i);
    int bp = i ? IDX(batch, i - 1) : -1;
    for (int g = bp + 1; g <= b; g++) g_gstart[g] = i;
}

// ---------------- tensor-core GEMM: C[M,128] = A[M,128] @ W[128,128] --------
__global__ __launch_bounds__(256) void gemm_tc_kernel(const float* __restrict__ A,
                                                      const float* __restrict__ W) {
    extern __shared__ __half smh[];
    __half* As = smh;                 // [128][PADH]
    __half* Bs = smh + 128 * PADH;    // [128][PADH]  (Bs[k][n])

    int tid = threadIdx.x;
    long long mbase = (long long)blockIdx.x * 128;

#pragma unroll
    for (int i = 0; i < 16; i++) {
        int idx = i * 256 + tid;
        int row = idx >> 5, c4 = idx & 31;
        long long grow = mbase + row;
        float4 v = (grow < NN) ? ((const float4*)A)[grow * 32 + c4]
                               : make_float4(0.f, 0.f, 0.f, 0.f);
        __half2* dst = (__half2*)(As + row * PADH + c4 * 4);
        dst[0] = __floats2half2_rn(v.x, v.y);
        dst[1] = __floats2half2_rn(v.z, v.w);
    }
#pragma unroll
    for (int i = 0; i < 16; i++) {
        int idx = i * 256 + tid;
        int row = idx >> 5, c4 = idx & 31;
        float4 v = ((const float4*)W)[row * 32 + c4];
        __half2* dst = (__half2*)(Bs + row * PADH + c4 * 4);
        dst[0] = __floats2half2_rn(v.x, v.y);
        dst[1] = __floats2half2_rn(v.z, v.w);
    }
    __syncthreads();

    int wid = tid >> 5, lane = tid & 31;
    int wm = (wid & 3) * 32;
    int wn = (wid >> 2) * 64;

    float acc[2][8][4];
#pragma unroll
    for (int mt = 0; mt < 2; mt++)
#pragma unroll
        for (int nt = 0; nt < 8; nt++)
#pragma unroll
            for (int q = 0; q < 4; q++) acc[mt][nt][q] = 0.f;

#pragma unroll
    for (int kk = 0; kk < 8; kk++) {
        unsigned a[2][4];
#pragma unroll
        for (int mt = 0; mt < 2; mt++) {
            int r = lane & 15, c = (lane >> 4) * 8;
            unsigned addr = (unsigned)__cvta_generic_to_shared(
                As + (wm + mt * 16 + r) * PADH + kk * 16 + c);
            asm volatile("ldmatrix.sync.aligned.m8n8.x4.shared.b16 {%0,%1,%2,%3}, [%4];"
                         : "=r"(a[mt][0]), "=r"(a[mt][1]), "=r"(a[mt][2]), "=r"(a[mt][3])
                         : "r"(addr));
        }
        unsigned b[8][2];
#pragma unroll
        for (int nt2 = 0; nt2 < 4; nt2++) {
            int krow = kk * 16 + ((lane >> 3) & 1) * 8 + (lane & 7);
            int ncol = wn + nt2 * 16 + (lane >> 4) * 8;
            unsigned addr = (unsigned)__cvta_generic_to_shared(Bs + krow * PADH + ncol);
            asm volatile("ldmatrix.sync.aligned.m8n8.x4.trans.shared.b16 {%0,%1,%2,%3}, [%4];"
                         : "=r"(b[nt2 * 2][0]), "=r"(b[nt2 * 2][1]),
                           "=r"(b[nt2 * 2 + 1][0]), "=r"(b[nt2 * 2 + 1][1])
                         : "r"(addr));
        }
#pragma unroll
        for (int mt = 0; mt < 2; mt++)
#pragma unroll
            for (int nt = 0; nt < 8; nt++)
                asm volatile("mma.sync.aligned.m16n8k16.row.col.f32.f16.f16.f32 "
                             "{%0,%1,%2,%3}, {%4,%5,%6,%7}, {%8,%9}, {%0,%1,%2,%3};"
                             : "+f"(acc[mt][nt][0]), "+f"(acc[mt][nt][1]),
                               "+f"(acc[mt][nt][2]), "+f"(acc[mt][nt][3])
                             : "r"(a[mt][0]), "r"(a[mt][1]), "r"(a[mt][2]), "r"(a[mt][3]),
                               "r"(b[nt][0]), "r"(b[nt][1]));
    }

    int r0 = lane >> 2, cq = (lane & 3) * 2;
#pragma unroll
    for (int mt = 0; mt < 2; mt++) {
        long long rowA = mbase + wm + mt * 16 + r0;
        long long rowB = rowA + 8;
#pragma unroll
        for (int nt = 0; nt < 8; nt++) {
            int col = wn + nt * 8 + cq;
            if (rowA < NN) {
                *(float2*)&g_xw[rowA * HD + col] = make_float2(acc[mt][nt][0], acc[mt][nt][1]);
                *(__half2*)&g_xwh[rowA * HD + col] = __floats2half2_rn(acc[mt][nt][0], acc[mt][nt][1]);
            }
            if (rowB < NN) {
                *(float2*)&g_xw[rowB * HD + col] = make_float2(acc[mt][nt][2], acc[mt][nt][3]);
                *(__half2*)&g_xwh[rowB * HD + col] = __floats2half2_rn(acc[mt][nt][2], acc[mt][nt][3]);
            }
        }
    }
}

// ---------------- edge scatter: aggh[dst] += xwh[src] * dinv[s]*dinv[d] -----
__global__ __launch_bounds__(256) void edge_kernel() {
    long long t = (long long)blockIdx.x * 256 + threadIdx.x;
    int e = (int)(t >> 4);
    if (e >= EE) return;
    int sub = threadIdx.x & 15;
    int s = g_src[e];
    int d = g_dst[e];
    float nm = __ldg(&g_dinv[s]) * __ldg(&g_dinv[d]);
    uint4 v = ((const uint4*)g_xwh)[(size_t)s * 16 + sub];
    __half2* hv = (__half2*)&v;
#pragma unroll
    for (int i = 0; i < 4; i++) {
        float2 f = __half22float2(hv[i]);
        hv[i] = __floats2half2_rn(f.x * nm, f.y * nm);
    }
    __half* p = g_aggh + (size_t)d * HD + sub * 8;
    asm volatile("red.global.add.noftz.v4.f16x2 [%0], {%1,%2,%3,%4};"
                 :: "l"(p), "r"(v.x), "r"(v.y), "r"(v.z), "r"(v.w)
                 : "memory");
}

// ---------------- node epilogue: h = relu(aggh + xw*dinv^2 + b) -------------
__global__ void node_kernel(const float* __restrict__ b) {
    int i = blockIdx.x * blockDim.x + threadIdx.x;   // over NN*32 float4s
    int node = i >> 5, q = i & 31;
    float di = g_dinv[node];
    float d2 = di * di;
    uint2 av = ((const uint2*)g_aggh)[i];
    float2 a0 = __half22float2(*(__half2*)&av.x);
    float2 a1 = __half22float2(*(__half2*)&av.y);
    float4 w  = ((const float4*)g_xw)[i];
    float4 bb = ((const float4*)b)[q];
    float4 h;
    h.x = fmaxf(fmaf(w.x, d2, a0.x) + bb.x, 0.f);
    h.y = fmaxf(fmaf(w.y, d2, a0.y) + bb.y, 0.f);
    h.z = fmaxf(fmaf(w.z, d2, a1.x) + bb.z, 0.f);
    h.w = fmaxf(fmaf(w.w, d2, a1.y) + bb.w, 0.f);
    ((float4*)g_h)[i] = h;
}

// ---------------- mean pool: one block per graph, no atomics ----------------
__global__ __launch_bounds__(128) void pool_kernel(float* __restrict__ out) {
    int g = blockIdx.x, t = threadIdx.x;
    int beg = g_gstart[g], end = g_gstart[g + 1];
    float s = 0.f;
#pragma unroll 4
    for (int n = beg; n < end; n++) s += g_h[(size_t)n * HD + t];
    out[g * HD + t] = s / fmaxf((float)(end - beg), 1.0f);
}

// ---------------- launch -----------------------------------------------------
extern "C" void kernel_launch(void* const* d_in, const int* in_sizes, int n_in,
                              void* d_out, int out_size) {
    const float *x = 0, *W1 = 0, *b1 = 0, *W2 = 0, *b2 = 0;
    const void  *ei = 0, *batch = 0;
    for (int i = 0; i < n_in; i++) {
        long long sz = in_sizes[i];
        if      (sz == (long long)NN * HD) x = (const float*)d_in[i];
        else if (sz == 2LL * EE)           ei = d_in[i];
        else if (sz == NN)                 batch = d_in[i];
        else if (sz == HD * HD) { if (!W1) W1 = (const float*)d_in[i];
                                  else     W2 = (const float*)d_in[i]; }
        else if (sz == HD)      { if (!b1) b1 = (const float*)d_in[i];
                                  else     b2 = (const float*)d_in[i]; }
    }
    float* out = (float*)d_out;

    static cudaStream_t sA = 0;
    static cudaEvent_t ev0 = 0, ev1 = 0, ev2 = 0, ev3 = 0;
    static void* aggh_addr = 0;
    static void* h_addr = 0;
    if (!sA) {
        cudaStreamCreateWithFlags(&sA, cudaStreamNonBlocking);
        cudaEventCreateWithFlags(&ev0, cudaEventDisableTiming);
        cudaEventCreateWithFlags(&ev1, cudaEventDisableTiming);
        cudaEventCreateWithFlags(&ev2, cudaEventDisableTiming);
        cudaEventCreateWithFlags(&ev3, cudaEventDisableTiming);
        cudaGetSymbolAddress(&aggh_addr, g_aggh);
        cudaGetSymbolAddress(&h_addr, g_h);
        cudaFuncSetAttribute((const void*)gemm_tc_kernel,
                             cudaFuncAttributeMaxDynamicSharedMemorySize,
                             2 * 128 * PADH * (int)sizeof(__half));
    }

    const int ZB    = (NN + 255) / 256;       // 157
    const int EB    = (EE + 255) / 256;       // 2500
    const int EDGB  = (EE * 16) / 256;        // 40000
    const int NODB  = (NN * 32) / 256;        // 5000
    const int GEMMB = (NN + 127) / 128;       // 313
    const int GSM   = 2 * 128 * PADH * (int)sizeof(__half);
    const size_t AGG_BYTES = (size_t)NN * HD * sizeof(__half);

    // fork: GEMM1 + aggh memset on sA; prep chain on main stream
    cudaEventRecord(ev0, 0);
    cudaStreamWaitEvent(sA, ev0, 0);
    cudaMemsetAsync(aggh_addr, 0, AGG_BYTES, sA);
    gemm_tc_kernel<<<GEMMB, 256, GSM, sA>>>(x, W1);
    cudaEventRecord(ev1, sA);

    detect_kernel<<<1, 256>>>((const unsigned int*)ei);
    zero_misc_kernel<<<ZB, 256>>>();
    conv_deg_kernel<<<EB, 256>>>(ei);
    dinv_kernel<<<ZB, 256>>>();
    gstart_kernel<<<ZB, 256>>>(batch);

    // join: layer-1 edge phase
    cudaStreamWaitEvent(0, ev1, 0);
    edge_kernel<<<EDGB, 256>>>();
    node_kernel<<<NODB, 256>>>(b1);
    cudaEventRecord(ev2, 0);

    // fork: re-zero accumulator on sA while main stream runs GEMM2
    cudaStreamWaitEvent(sA, ev2, 0);
    cudaMemsetAsync(aggh_addr, 0, AGG_BYTES, sA);
    cudaEventRecord(ev3, sA);
    gemm_tc_kernel<<<GEMMB, 256, GSM>>>((const float*)h_addr, W2);

    // join: layer-2 edge phase
    cudaStreamWaitEvent(0, ev3, 0);
    edge_kernel<<<EDGB, 256>>>();
    node_kernel<<<NODB, 256>>>(b2);

    // pool
    pool_kernel<<<GG, 128>>>(out);
}